// round 3
// baseline (speedup 1.0000x reference)
#include <cuda_runtime.h>
#include <cuda_bf16.h>

// NnInteractionTokenizer: bond = x[row]*x[col]; local_field = segsum(bond, row);
// tokens = relu(relu([x, lf] @ w1^T + b1) @ w2^T + b2)
//
// Algebraic simplification: local_field[r] = x[r] * sum_{e: row[e]=r} x[col[e]]
// -> edge phase only accumulates x[col[e]] into g_acc[row[e]] (one gather, one
//    float REDG per edge); the x[r] multiply folds into the node phase.

#define N_NODES 100000
#define N_EDGES 6400000
#define TD 16
#define EPT 8   // edges per thread in the edge kernel

// Scratch (no device allocation allowed -> __device__ globals)
__device__ float g_acc[N_NODES];
__device__ int   g_is64;

// ---------------------------------------------------------------------------
// Probe: edge_index dtype detection. The reference asks for int64, but JAX
// without x64 silently yields int32. Interpreted as uint32 words, int64 data
// (values < 2^17, little-endian) has all odd words == 0; int32 data has random
// values in [0, 100000) -> P(256 consecutive zero odd-words) ~ 0.
// ---------------------------------------------------------------------------
__global__ void probe_kernel(const unsigned int* __restrict__ w) {
    __shared__ int nz;
    if (threadIdx.x == 0) nz = 0;
    __syncthreads();
    unsigned int v = w[threadIdx.x * 2 + 1];
    if (v != 0u) atomicAdd(&nz, 1);
    __syncthreads();
    if (threadIdx.x == 0) g_is64 = (nz == 0) ? 1 : 0;
}

__global__ void zero_kernel() {
    int i = blockIdx.x * blockDim.x + threadIdx.x;
    if (i < N_NODES) g_acc[i] = 0.0f;
}

// ---------------------------------------------------------------------------
// Edge phase: EPT edges per thread, vectorized index loads, batched gathers
// (MLP=EPT) then EPT REDG.F32 to L2-resident g_acc.
// ---------------------------------------------------------------------------
__global__ void __launch_bounds__(256) edge_kernel(const void* __restrict__ ei,
                                                   const float* __restrict__ x) {
    const int tid = blockIdx.x * blockDim.x + threadIdx.x;
    const long long base = (long long)tid * EPT;
    if (base >= N_EDGES) return;

    int r[EPT], c[EPT];
    if (g_is64) {
        const longlong2* row = (const longlong2*)ei;          // edge_index[0]
        const longlong2* col = row + (N_EDGES / 2);           // edge_index[1]
#pragma unroll
        for (int k = 0; k < EPT / 2; k++) {
            longlong2 rv = __ldg(&row[base / 2 + k]);
            r[2 * k] = (int)rv.x; r[2 * k + 1] = (int)rv.y;
        }
#pragma unroll
        for (int k = 0; k < EPT / 2; k++) {
            longlong2 cv = __ldg(&col[base / 2 + k]);
            c[2 * k] = (int)cv.x; c[2 * k + 1] = (int)cv.y;
        }
    } else {
        const int4* row = (const int4*)ei;
        const int4* col = row + (N_EDGES / 4);
#pragma unroll
        for (int k = 0; k < EPT / 4; k++) {
            int4 rv = __ldg(&row[base / 4 + k]);
            r[4 * k] = rv.x; r[4 * k + 1] = rv.y; r[4 * k + 2] = rv.z; r[4 * k + 3] = rv.w;
        }
#pragma unroll
        for (int k = 0; k < EPT / 4; k++) {
            int4 cv = __ldg(&col[base / 4 + k]);
            c[4 * k] = cv.x; c[4 * k + 1] = cv.y; c[4 * k + 2] = cv.z; c[4 * k + 3] = cv.w;
        }
    }

    float v[EPT];
#pragma unroll
    for (int k = 0; k < EPT; k++) v[k] = __ldg(&x[c[k]]);
#pragma unroll
    for (int k = 0; k < EPT; k++) atomicAdd(&g_acc[r[k]], v[k]);
}

// ---------------------------------------------------------------------------
// Node phase: per-node 2->16->16 MLP. Weights staged in smem (broadcast LDS,
// conflict-free). Output via 4x STG.128 per node.
// ---------------------------------------------------------------------------
__global__ void __launch_bounds__(128) node_kernel(const float* __restrict__ x,
                                                   const float* __restrict__ w1,
                                                   const float* __restrict__ b1,
                                                   const float* __restrict__ w2,
                                                   const float* __restrict__ b2,
                                                   float* __restrict__ out) {
    __shared__ float sw1[2 * TD];
    __shared__ float sb1[TD];
    __shared__ float sw2[TD * TD];
    __shared__ float sb2[TD];

    const int t = threadIdx.x;
    if (t < 2 * TD) sw1[t] = w1[t];
    if (t < TD) { sb1[t] = b1[t]; sb2[t] = b2[t]; }
    for (int i = t; i < TD * TD; i += blockDim.x) sw2[i] = w2[i];
    __syncthreads();

    const int n = blockIdx.x * blockDim.x + t;
    if (n >= N_NODES) return;

    const float s  = x[n];
    const float lf = s * g_acc[n];

    float h[TD];
#pragma unroll
    for (int j = 0; j < TD; j++) {
        float v = fmaf(sw1[2 * j + 1], lf, fmaf(sw1[2 * j], s, sb1[j]));
        h[j] = v > 0.0f ? v : 0.0f;
    }

    float4* o = (float4*)(out + (size_t)n * TD);
#pragma unroll
    for (int k4 = 0; k4 < 4; k4++) {
        float4 res;
        float* rp = (float*)&res;
#pragma unroll
        for (int kk = 0; kk < 4; kk++) {
            const int k = k4 * 4 + kk;
            float v = sb2[k];
#pragma unroll
            for (int j = 0; j < TD; j++) v = fmaf(sw2[k * TD + j], h[j], v);
            rp[kk] = v > 0.0f ? v : 0.0f;
        }
        o[k4] = res;
    }
}

extern "C" void kernel_launch(void* const* d_in, const int* in_sizes, int n_in,
                              void* d_out, int out_size) {
    const float* x  = (const float*)d_in[0];
    const void*  ei = d_in[1];
    const float* w1 = (const float*)d_in[2];
    const float* b1 = (const float*)d_in[3];
    const float* w2 = (const float*)d_in[4];
    const float* b2 = (const float*)d_in[5];
    float* out = (float*)d_out;

    probe_kernel<<<1, 256>>>((const unsigned int*)ei);
    zero_kernel<<<(N_NODES + 255) / 256, 256>>>();
    edge_kernel<<<N_EDGES / EPT / 256, 256>>>(ei, x);
    node_kernel<<<(N_NODES + 127) / 128, 128>>>(x, w1, b1, w2, b2, out);
}